// round 5
// baseline (speedup 1.0000x reference)
#include <cuda_runtime.h>
#include <math.h>

// ---------------------------------------------------------------------------
// Problem constants
//   B=4, N=16384 (H=W=128), C=128, HEADS=2, dh=64, SR=4 -> N'=1024
// ---------------------------------------------------------------------------
#define BATCH   4
#define NQ      16384
#define C_DIM   128
#define HEADS   2
#define DH      64
#define NKV     1024      // (128/4)^2
#define KCONV   2048      // 4*4*128 patch features

// Scratch (allocation-free rule: __device__ globals)
__device__ float g_q [BATCH * NQ  * C_DIM];   // (B,N,C)  Q projection
__device__ float g_xr[BATCH * NKV * C_DIM];   // (B,N',C) conv+LN result
__device__ float g_k [BATCH * NKV * C_DIM];   // (B,N',C)
__device__ float g_v [BATCH * NKV * C_DIM];   // (B,N',C)
__device__ float g_ao[BATCH * NQ  * C_DIM];   // (B,N,C)  attention output

// ---------------------------------------------------------------------------
// Generic GEMM: out[M,128] = A[M,128] @ W[128,128]
// BM=64, BN=128 (full), BK=32 chunks. 256 threads, each owns 4x8 outputs.
// ---------------------------------------------------------------------------
__global__ __launch_bounds__(256)
void gemm128_kernel(const float* __restrict__ A, const float* __restrict__ W,
                    float* __restrict__ out, int M) {
    __shared__ float sA[64][33];
    __shared__ float sB[32][128];
    int m0 = blockIdx.x << 6;
    int tid = threadIdx.x;
    int ty = tid >> 4, tx = tid & 15;
    float acc[4][8];
#pragma unroll
    for (int i = 0; i < 4; i++)
#pragma unroll
        for (int j = 0; j < 8; j++) acc[i][j] = 0.f;

    for (int k0 = 0; k0 < 128; k0 += 32) {
        __syncthreads();
        {   // load A chunk: 64x32, 2 float4 per thread (coalesced)
            int rr = tid >> 3, c4 = tid & 7;
#pragma unroll
            for (int hh = 0; hh < 2; hh++) {
                int row = rr + (hh << 5);
                float4 v = *(const float4*)&A[(size_t)(m0 + row) * 128 + k0 + (c4 << 2)];
                sA[row][(c4 << 2) + 0] = v.x;
                sA[row][(c4 << 2) + 1] = v.y;
                sA[row][(c4 << 2) + 2] = v.z;
                sA[row][(c4 << 2) + 3] = v.w;
            }
            // load W chunk: 32x128, 4 float4 per thread
#pragma unroll
            for (int i = 0; i < 4; i++) {
                int f = tid + (i << 8);
                int rw = f >> 5, c = f & 31;
                *(float4*)&sB[rw][c << 2] = *(const float4*)&W[(k0 + rw) * 128 + (c << 2)];
            }
        }
        __syncthreads();
#pragma unroll
        for (int k = 0; k < 32; k++) {
            float a[4], bb[8];
#pragma unroll
            for (int i = 0; i < 4; i++) a[i] = sA[ty + (i << 4)][k];
#pragma unroll
            for (int j = 0; j < 8; j++) bb[j] = sB[k][tx + (j << 4)];
#pragma unroll
            for (int i = 0; i < 4; i++)
#pragma unroll
                for (int j = 0; j < 8; j++) acc[i][j] += a[i] * bb[j];
        }
    }
#pragma unroll
    for (int i = 0; i < 4; i++)
#pragma unroll
        for (int j = 0; j < 8; j++)
            out[(size_t)(m0 + ty + (i << 4)) * 128 + tx + (j << 4)] = acc[i][j];
}

// ---------------------------------------------------------------------------
// Fused SR conv (4x4 stride-4 patch GEMM, K=2048) + bias + LayerNorm
// BM=32 rows per block -> 128 blocks (better SM coverage for M=4096).
// x: (B,128,128,C) NHWC. Wsr flat: [2048][128] where k = (kh*4+kw)*128+ci.
// ---------------------------------------------------------------------------
__global__ __launch_bounds__(256)
void conv_ln_kernel(const float* __restrict__ x, const float* __restrict__ Wsr,
                    const float* __restrict__ bias, const float* __restrict__ gamma,
                    const float* __restrict__ beta, float* __restrict__ out) {
    __shared__ float sA[32][33];
    __shared__ float sB[32][128];
    __shared__ float sMu[32], sRs[32];
    int m0 = blockIdx.x << 5;
    int tid = threadIdx.x;
    int ty = tid >> 4, tx = tid & 15;
    float acc[2][8];
#pragma unroll
    for (int i = 0; i < 2; i++)
#pragma unroll
        for (int j = 0; j < 8; j++) acc[i][j] = 0.f;

    for (int c = 0; c < 64; c++) {
        int k0  = c << 5;
        int kh  = k0 >> 9;
        int kw  = (k0 >> 7) & 3;
        int ci0 = k0 & 127;
        __syncthreads();
        {   // gather A chunk: 32 rows x 32 contiguous channels of one pixel
            int rr = tid >> 3, c4 = tid & 7;
            int m  = m0 + rr;
            int b  = m >> 10, pos = m & 1023, oh = pos >> 5, ow = pos & 31;
            const float* px = x + ((size_t)((b * 128 + (oh << 2) + kh) * 128 + (ow << 2) + kw)) * 128 + ci0;
            float4 v = *(const float4*)(px + (c4 << 2));
            sA[rr][(c4 << 2) + 0] = v.x;
            sA[rr][(c4 << 2) + 1] = v.y;
            sA[rr][(c4 << 2) + 2] = v.z;
            sA[rr][(c4 << 2) + 3] = v.w;
        }
#pragma unroll
        for (int i = 0; i < 4; i++) {
            int f = tid + (i << 8);
            int rw = f >> 5, cc = f & 31;
            *(float4*)&sB[rw][cc << 2] = *(const float4*)&Wsr[(size_t)(k0 + rw) * 128 + (cc << 2)];
        }
        __syncthreads();
#pragma unroll
        for (int k = 0; k < 32; k++) {
            float a0 = sA[ty][k], a1 = sA[ty + 16][k];
            float bb[8];
#pragma unroll
            for (int j = 0; j < 8; j++) bb[j] = sB[k][tx + (j << 4)];
#pragma unroll
            for (int j = 0; j < 8; j++) {
                acc[0][j] += a0 * bb[j];
                acc[1][j] += a1 * bb[j];
            }
        }
    }

    // epilogue: +bias, LayerNorm over C=128 (each row held by 16 threads x 8 cols)
    __syncthreads();
    float v[2][8], ps[2] = {0.f, 0.f}, ps2[2] = {0.f, 0.f};
#pragma unroll
    for (int i = 0; i < 2; i++)
#pragma unroll
        for (int j = 0; j < 8; j++) {
            float t = acc[i][j] + bias[tx + (j << 4)];
            v[i][j] = t;
            ps[i]  += t;
            ps2[i] += t * t;
        }
    float* red = &sB[0][0];   // reuse: [0..511] sums, [512..1023] sumsq
#pragma unroll
    for (int i = 0; i < 2; i++) {
        int row = ty + (i << 4);
        red[row * 16 + tx]       = ps[i];
        red[512 + row * 16 + tx] = ps2[i];
    }
    __syncthreads();
    if (tid < 32) {
        float s = 0.f, s2 = 0.f;
#pragma unroll
        for (int t = 0; t < 16; t++) {
            s  += red[tid * 16 + t];
            s2 += red[512 + tid * 16 + t];
        }
        float mu  = s  * 0.0078125f;
        float var = s2 * 0.0078125f - mu * mu;
        sMu[tid] = mu;
        sRs[tid] = rsqrtf(var + 1e-6f);
    }
    __syncthreads();
#pragma unroll
    for (int i = 0; i < 2; i++)
#pragma unroll
        for (int j = 0; j < 8; j++) {
            int row = ty + (i << 4), col = tx + (j << 4);
            out[(size_t)(m0 + row) * 128 + col] =
                (v[i][j] - sMu[row]) * sRs[row] * gamma[col] + beta[col];
        }
}

// ---------------------------------------------------------------------------
// Flash-style attention: per block (b, h, 64-query tile), Nk=1024 in 16 chunks
// of 64 keys. 48KB static smem with XOR swizzle (conflict-free, no padding).
// ---------------------------------------------------------------------------
__device__ __forceinline__ int swz4(int row, int c4) {         // float4-granular
    return (row << 6) + ((c4 ^ (row & 15)) << 2);
}
__device__ __forceinline__ int swzs(int row, int col) {        // scalar
    return (row << 6) + ((((col >> 2) ^ (row & 15)) << 2) | (col & 3));
}

__global__ __launch_bounds__(256)
void attn_kernel(const float* __restrict__ Q, const float* __restrict__ K,
                 const float* __restrict__ V, float* __restrict__ O) {
    __shared__ float sQ [4096];   // [q][d], swizzled, pre-scaled
    __shared__ float sKS[4096];   // [k][d] as K, then [q][k] as S/P (aliased)
    __shared__ float sV [4096];   // [k][d], swizzled

    int b  = blockIdx.z, h = blockIdx.y;
    int n0 = blockIdx.x << 6;
    int tid = threadIdx.x;

    // load + scale Q tile (64x64)
    const float* qb = Q + ((size_t)(b * NQ + n0)) * C_DIM + h * DH;
#pragma unroll
    for (int i = 0; i < 4; i++) {
        int f = tid + (i << 8);
        int r = f >> 4, c4 = f & 15;
        float4 v = *(const float4*)(qb + (size_t)r * C_DIM + (c4 << 2));
        float* d = &sQ[swz4(r, c4)];
        d[0] = v.x * 0.125f; d[1] = v.y * 0.125f; d[2] = v.z * 0.125f; d[3] = v.w * 0.125f;
    }

    const float* kb_ = K + (size_t)(b * NKV) * C_DIM + h * DH;
    const float* vb_ = V + (size_t)(b * NKV) * C_DIM + h * DH;

    int ty = tid >> 4, tx = tid & 15;   // phase-1 persona
    int g  = tid >> 2, r4 = tid & 3;    // phase-2 persona (4 threads / query)

    float m = -1e30f, l = 0.f;
    float acc[16];
#pragma unroll
    for (int t = 0; t < 16; t++) acc[t] = 0.f;

#pragma unroll 1
    for (int kb = 0; kb < 16; kb++) {
        __syncthreads();   // prior iteration fully consumed sKS/sV
#pragma unroll
        for (int i = 0; i < 4; i++) {
            int f = tid + (i << 8);
            int r = f >> 4, c4 = f & 15;
            size_t go = (size_t)((kb << 6) + r) * C_DIM + (c4 << 2);
            *(float4*)&sKS[swz4(r, c4)] = *(const float4*)(kb_ + go);
            *(float4*)&sV [swz4(r, c4)] = *(const float4*)(vb_ + go);
        }
        __syncthreads();

        // phase 1: S[64x64] = Q * K^T (thread owns q=ty+16i, k=tx+16j)
        float s[4][4];
#pragma unroll
        for (int i = 0; i < 4; i++)
#pragma unroll
            for (int j = 0; j < 4; j++) s[i][j] = 0.f;
#pragma unroll
        for (int d4 = 0; d4 < 16; d4++) {
            float4 a[4], bb[4];
#pragma unroll
            for (int i = 0; i < 4; i++) a[i]  = *(const float4*)&sQ [swz4(ty + (i << 4), d4)];
#pragma unroll
            for (int j = 0; j < 4; j++) bb[j] = *(const float4*)&sKS[swz4(tx + (j << 4), d4)];
#pragma unroll
            for (int i = 0; i < 4; i++)
#pragma unroll
                for (int j = 0; j < 4; j++)
                    s[i][j] += a[i].x * bb[j].x + a[i].y * bb[j].y
                             + a[i].z * bb[j].z + a[i].w * bb[j].w;
        }
        __syncthreads();   // done reading sKS as K
#pragma unroll
        for (int i = 0; i < 4; i++)
#pragma unroll
            for (int j = 0; j < 4; j++)
                sKS[swzs(ty + (i << 4), tx + (j << 4))] = s[i][j];
        __syncthreads();

        // phase 2a: online softmax (thread owns query g, cols r4*16..+15)
        float p[16];
#pragma unroll
        for (int t4 = 0; t4 < 4; t4++) {
            float4 pv = *(const float4*)&sKS[swz4(g, (r4 << 2) + t4)];
            p[t4 * 4 + 0] = pv.x; p[t4 * 4 + 1] = pv.y;
            p[t4 * 4 + 2] = pv.z; p[t4 * 4 + 3] = pv.w;
        }
        float cmax = -1e30f;
#pragma unroll
        for (int t = 0; t < 16; t++) cmax = fmaxf(cmax, p[t]);
        cmax = fmaxf(cmax, __shfl_xor_sync(0xffffffffu, cmax, 1));
        cmax = fmaxf(cmax, __shfl_xor_sync(0xffffffffu, cmax, 2));
        float mn    = fmaxf(m, cmax);
        float alpha = __expf(m - mn);
        float psum  = 0.f;
#pragma unroll
        for (int t = 0; t < 16; t++) {
            p[t] = __expf(p[t] - mn);
            psum += p[t];
        }
#pragma unroll
        for (int t4 = 0; t4 < 4; t4++) {
            float4 pv = make_float4(p[t4 * 4 + 0], p[t4 * 4 + 1],
                                    p[t4 * 4 + 2], p[t4 * 4 + 3]);
            *(float4*)&sKS[swz4(g, (r4 << 2) + t4)] = pv;
        }
        psum += __shfl_xor_sync(0xffffffffu, psum, 1);
        psum += __shfl_xor_sync(0xffffffffu, psum, 2);
        l = l * alpha + psum;
        m = mn;
#pragma unroll
        for (int t = 0; t < 16; t++) acc[t] *= alpha;
        __syncthreads();   // all P written

        // phase 2b: O += P * V (thread owns dims r4*16..+15 of query g).
        // P row read as float4 over the key dim (swizzle is float4-granular,
        // so kk..kk+3 within an aligned group are contiguous).
#pragma unroll
        for (int kk4 = 0; kk4 < 16; kk4++) {
            float4 p4 = *(const float4*)&sKS[swz4(g, kk4)];
            float pp[4] = {p4.x, p4.y, p4.z, p4.w};
#pragma unroll
            for (int e = 0; e < 4; e++) {
                int kk = (kk4 << 2) + e;
                float pv = pp[e];
#pragma unroll
                for (int t4 = 0; t4 < 4; t4++) {
                    float4 vv = *(const float4*)&sV[swz4(kk, (r4 << 2) + t4)];
                    acc[t4 * 4 + 0] += pv * vv.x;
                    acc[t4 * 4 + 1] += pv * vv.y;
                    acc[t4 * 4 + 2] += pv * vv.z;
                    acc[t4 * 4 + 3] += pv * vv.w;
                }
            }
        }
    }

    // epilogue: normalize and write (B,N,C) with heads concatenated
    float inv = 1.f / l;
    float* ob = O + ((size_t)(b * NQ + n0 + g)) * C_DIM + h * DH + (r4 << 4);
#pragma unroll
    for (int t4 = 0; t4 < 4; t4++) {
        float4 o = make_float4(acc[t4 * 4 + 0] * inv, acc[t4 * 4 + 1] * inv,
                               acc[t4 * 4 + 2] * inv, acc[t4 * 4 + 3] * inv);
        *(float4*)(ob + (t4 << 2)) = o;
    }
}

// ---------------------------------------------------------------------------
// Launch. Inputs (metadata order): x, Wq, Wk, Wv, Wproj, sr_kernel, sr_bias,
// gamma, beta. Output: (B,N,C) float32. All launches on default stream.
// ---------------------------------------------------------------------------
extern "C" void kernel_launch(void* const* d_in, const int* in_sizes, int n_in,
                              void* d_out, int out_size) {
    const float* x     = (const float*)d_in[0];
    const float* Wq    = (const float*)d_in[1];
    const float* Wk    = (const float*)d_in[2];
    const float* Wv    = (const float*)d_in[3];
    const float* Wp    = (const float*)d_in[4];
    const float* Wsr   = (const float*)d_in[5];
    const float* bias  = (const float*)d_in[6];
    const float* gamma = (const float*)d_in[7];
    const float* beta  = (const float*)d_in[8];

    float *q, *xr, *k, *v, *ao;
    cudaGetSymbolAddress((void**)&q,  g_q);
    cudaGetSymbolAddress((void**)&xr, g_xr);
    cudaGetSymbolAddress((void**)&k,  g_k);
    cudaGetSymbolAddress((void**)&v,  g_v);
    cudaGetSymbolAddress((void**)&ao, g_ao);

    gemm128_kernel<<<(BATCH * NQ) / 64, 256>>>(x, Wq, q, BATCH * NQ);          // Q proj
    conv_ln_kernel<<<(BATCH * NKV) / 32, 256>>>(x, Wsr, bias, gamma, beta, xr); // SR + LN
    gemm128_kernel<<<(BATCH * NKV) / 64, 256>>>(xr, Wk, k, BATCH * NKV);       // K proj
    gemm128_kernel<<<(BATCH * NKV) / 64, 256>>>(xr, Wv, v, BATCH * NKV);       // V proj
    attn_kernel<<<dim3(NQ / 64, HEADS, BATCH), 256>>>(q, k, v, ao);            // attention
    gemm128_kernel<<<(BATCH * NQ) / 64, 256>>>(ao, Wp, (float*)d_out, BATCH * NQ); // out proj
}

// round 6
// speedup vs baseline: 4.7728x; 4.7728x over previous
#include <cuda_runtime.h>
#include <math.h>

// ---------------------------------------------------------------------------
// Problem constants
//   B=4, N=16384 (H=W=128), C=128, HEADS=2, dh=64, SR=4 -> N'=1024
// ---------------------------------------------------------------------------
#define BATCH   4
#define NQ      16384
#define C_DIM   128
#define HEADS   2
#define DH      64
#define NKV     1024
#define QTILE   128
#define KCH     32

// Scratch (allocation-free rule: __device__ globals)
__device__ float g_q [BATCH * NQ  * C_DIM];
__device__ float g_xr[BATCH * NKV * C_DIM];
__device__ float g_k [BATCH * NKV * C_DIM];
__device__ float g_v [BATCH * NKV * C_DIM];
__device__ float g_ao[BATCH * NQ  * C_DIM];

// ---------------------------------------------------------------------------
// tf32 helpers
// ---------------------------------------------------------------------------
__device__ __forceinline__ unsigned f2tf(float x) {
    unsigned r;
    asm("cvt.rna.tf32.f32 %0, %1;" : "=r"(r) : "f"(x));
    return r;
}

__device__ __forceinline__ void mma_tf32(float& d0, float& d1, float& d2, float& d3,
                                         unsigned a0, unsigned a1, unsigned a2, unsigned a3,
                                         unsigned b0, unsigned b1) {
    asm volatile(
        "mma.sync.aligned.m16n8k8.row.col.f32.tf32.tf32.f32 "
        "{%0,%1,%2,%3},{%4,%5,%6,%7},{%8,%9},{%0,%1,%2,%3};"
        : "+f"(d0), "+f"(d1), "+f"(d2), "+f"(d3)
        : "r"(a0), "r"(a1), "r"(a2), "r"(a3), "r"(b0), "r"(b1));
}

// ---------------------------------------------------------------------------
// Generic GEMM: out[M,128] = A[M,128] @ W[128,128]  (fp32, unchanged)
// ---------------------------------------------------------------------------
__global__ __launch_bounds__(256)
void gemm128_kernel(const float* __restrict__ A, const float* __restrict__ W,
                    float* __restrict__ out, int M) {
    __shared__ float sA[64][33];
    __shared__ float sB[32][128];
    int m0 = blockIdx.x << 6;
    int tid = threadIdx.x;
    int ty = tid >> 4, tx = tid & 15;
    float acc[4][8];
#pragma unroll
    for (int i = 0; i < 4; i++)
#pragma unroll
        for (int j = 0; j < 8; j++) acc[i][j] = 0.f;

    for (int k0 = 0; k0 < 128; k0 += 32) {
        __syncthreads();
        {
            int rr = tid >> 3, c4 = tid & 7;
#pragma unroll
            for (int hh = 0; hh < 2; hh++) {
                int row = rr + (hh << 5);
                float4 v = *(const float4*)&A[(size_t)(m0 + row) * 128 + k0 + (c4 << 2)];
                sA[row][(c4 << 2) + 0] = v.x;
                sA[row][(c4 << 2) + 1] = v.y;
                sA[row][(c4 << 2) + 2] = v.z;
                sA[row][(c4 << 2) + 3] = v.w;
            }
#pragma unroll
            for (int i = 0; i < 4; i++) {
                int f = tid + (i << 8);
                int rw = f >> 5, c = f & 31;
                *(float4*)&sB[rw][c << 2] = *(const float4*)&W[(k0 + rw) * 128 + (c << 2)];
            }
        }
        __syncthreads();
#pragma unroll
        for (int k = 0; k < 32; k++) {
            float a[4], bb[8];
#pragma unroll
            for (int i = 0; i < 4; i++) a[i] = sA[ty + (i << 4)][k];
#pragma unroll
            for (int j = 0; j < 8; j++) bb[j] = sB[k][tx + (j << 4)];
#pragma unroll
            for (int i = 0; i < 4; i++)
#pragma unroll
                for (int j = 0; j < 8; j++) acc[i][j] += a[i] * bb[j];
        }
    }
#pragma unroll
    for (int i = 0; i < 4; i++)
#pragma unroll
        for (int j = 0; j < 8; j++)
            out[(size_t)(m0 + ty + (i << 4)) * 128 + tx + (j << 4)] = acc[i][j];
}

// ---------------------------------------------------------------------------
// Fused SR conv (4x4 stride-4 patch GEMM) + bias + LayerNorm  (unchanged)
// ---------------------------------------------------------------------------
__global__ __launch_bounds__(256)
void conv_ln_kernel(const float* __restrict__ x, const float* __restrict__ Wsr,
                    const float* __restrict__ bias, const float* __restrict__ gamma,
                    const float* __restrict__ beta, float* __restrict__ out) {
    __shared__ float sA[32][33];
    __shared__ float sB[32][128];
    __shared__ float sMu[32], sRs[32];
    int m0 = blockIdx.x << 5;
    int tid = threadIdx.x;
    int ty = tid >> 4, tx = tid & 15;
    float acc[2][8];
#pragma unroll
    for (int i = 0; i < 2; i++)
#pragma unroll
        for (int j = 0; j < 8; j++) acc[i][j] = 0.f;

    for (int c = 0; c < 64; c++) {
        int k0  = c << 5;
        int kh  = k0 >> 9;
        int kw  = (k0 >> 7) & 3;
        int ci0 = k0 & 127;
        __syncthreads();
        {
            int rr = tid >> 3, c4 = tid & 7;
            int m  = m0 + rr;
            int b  = m >> 10, pos = m & 1023, oh = pos >> 5, ow = pos & 31;
            const float* px = x + ((size_t)((b * 128 + (oh << 2) + kh) * 128 + (ow << 2) + kw)) * 128 + ci0;
            float4 v = *(const float4*)(px + (c4 << 2));
            sA[rr][(c4 << 2) + 0] = v.x;
            sA[rr][(c4 << 2) + 1] = v.y;
            sA[rr][(c4 << 2) + 2] = v.z;
            sA[rr][(c4 << 2) + 3] = v.w;
        }
#pragma unroll
        for (int i = 0; i < 4; i++) {
            int f = tid + (i << 8);
            int rw = f >> 5, cc = f & 31;
            *(float4*)&sB[rw][cc << 2] = *(const float4*)&Wsr[(size_t)(k0 + rw) * 128 + (cc << 2)];
        }
        __syncthreads();
#pragma unroll
        for (int k = 0; k < 32; k++) {
            float a0 = sA[ty][k], a1 = sA[ty + 16][k];
            float bb[8];
#pragma unroll
            for (int j = 0; j < 8; j++) bb[j] = sB[k][tx + (j << 4)];
#pragma unroll
            for (int j = 0; j < 8; j++) {
                acc[0][j] += a0 * bb[j];
                acc[1][j] += a1 * bb[j];
            }
        }
    }

    __syncthreads();
    float v[2][8], ps[2] = {0.f, 0.f}, ps2[2] = {0.f, 0.f};
#pragma unroll
    for (int i = 0; i < 2; i++)
#pragma unroll
        for (int j = 0; j < 8; j++) {
            float t = acc[i][j] + bias[tx + (j << 4)];
            v[i][j] = t;
            ps[i]  += t;
            ps2[i] += t * t;
        }
    float* red = &sB[0][0];
#pragma unroll
    for (int i = 0; i < 2; i++) {
        int row = ty + (i << 4);
        red[row * 16 + tx]       = ps[i];
        red[512 + row * 16 + tx] = ps2[i];
    }
    __syncthreads();
    if (tid < 32) {
        float s = 0.f, s2 = 0.f;
#pragma unroll
        for (int t = 0; t < 16; t++) {
            s  += red[tid * 16 + t];
            s2 += red[512 + tid * 16 + t];
        }
        float mu  = s  * 0.0078125f;
        float var = s2 * 0.0078125f - mu * mu;
        sMu[tid] = mu;
        sRs[tid] = rsqrtf(var + 1e-6f);
    }
    __syncthreads();
#pragma unroll
    for (int i = 0; i < 2; i++)
#pragma unroll
        for (int j = 0; j < 8; j++) {
            int row = ty + (i << 4), col = tx + (j << 4);
            out[(size_t)(m0 + row) * 128 + col] =
                (v[i][j] - sMu[row]) * sRs[row] * gamma[col] + beta[col];
        }
}

// ---------------------------------------------------------------------------
// tf32 tensor-core flash attention.
// Block: 256 threads (8 warps), 128 queries; key loop: 32 chunks of 32.
// Warp w owns query rows [w*16, w*16+16). mma m16n8k8 tf32.
// smem strides tuned for conflict-free fragment reads:
//   sK stride 68 (bank = 4*key + d), sV stride 72 (bank = 8*key + d),
//   sP stride 36 (bank = 4*row + col).
// ---------------------------------------------------------------------------
__global__ __launch_bounds__(256)
void attn_mma_kernel(const float* __restrict__ Q, const float* __restrict__ K,
                     const float* __restrict__ V, float* __restrict__ O) {
    __shared__ float sK[KCH * 68];     // [key][d]
    __shared__ float sV[KCH * 72];     // [key][d]
    __shared__ float sP[QTILE * 36];   // [q][key]

    int b  = blockIdx.z, h = blockIdx.y;
    int n0 = blockIdx.x * QTILE;
    int tid  = threadIdx.x;
    int w    = tid >> 5;
    int lane = tid & 31;
    int gid  = lane >> 2;     // group id (row within 16-row tile)
    int tig  = lane & 3;      // thread in group

    // --- preload Q fragments (pre-scaled, tf32) : 8 k-steps x 4 regs ---
    unsigned qa[8][4];
    {
        const float* qb = Q + ((size_t)(b * NQ + n0 + w * 16)) * C_DIM + h * DH;
#pragma unroll
        for (int ks = 0; ks < 8; ks++) {
            int c = ks * 8 + tig;
            qa[ks][0] = f2tf(qb[(size_t)gid       * C_DIM + c    ] * 0.125f);
            qa[ks][1] = f2tf(qb[(size_t)(gid + 8) * C_DIM + c    ] * 0.125f);
            qa[ks][2] = f2tf(qb[(size_t)gid       * C_DIM + c + 4] * 0.125f);
            qa[ks][3] = f2tf(qb[(size_t)(gid + 8) * C_DIM + c + 4] * 0.125f);
        }
    }

    const float* kb_ = K + (size_t)(b * NKV) * C_DIM + h * DH;
    const float* vb_ = V + (size_t)(b * NKV) * C_DIM + h * DH;

    float oacc[8][4];                 // 8 d-tiles x (r:2cols, r+8:2cols)
#pragma unroll
    for (int i = 0; i < 8; i++)
#pragma unroll
        for (int j = 0; j < 4; j++) oacc[i][j] = 0.f;
    float m0r = -1e30f, m1r = -1e30f, l0 = 0.f, l1 = 0.f;

#pragma unroll 1
    for (int kc = 0; kc < NKV / KCH; kc++) {
        __syncthreads();   // prior chunk's sK/sV reads complete
        // load K,V chunk (32 keys x 64 floats each), convert to tf32 on store
#pragma unroll
        for (int i = 0; i < 2; i++) {
            int f = tid + (i << 8);
            int row = f >> 4, c4 = f & 15;
            size_t go = (size_t)(kc * KCH + row) * C_DIM + (c4 << 2);
            float4 kv = *(const float4*)(kb_ + go);
            float4 vv = *(const float4*)(vb_ + go);
            float4 kt, vt;
            kt.x = __uint_as_float(f2tf(kv.x)); kt.y = __uint_as_float(f2tf(kv.y));
            kt.z = __uint_as_float(f2tf(kv.z)); kt.w = __uint_as_float(f2tf(kv.w));
            vt.x = __uint_as_float(f2tf(vv.x)); vt.y = __uint_as_float(f2tf(vv.y));
            vt.z = __uint_as_float(f2tf(vv.z)); vt.w = __uint_as_float(f2tf(vv.w));
            *(float4*)&sK[row * 68 + (c4 << 2)] = kt;
            *(float4*)&sV[row * 72 + (c4 << 2)] = vt;
        }
        __syncthreads();

        // ---- phase 1: S[16x32] = Q * K^T ----
        float sacc[4][4];
#pragma unroll
        for (int i = 0; i < 4; i++)
#pragma unroll
            for (int j = 0; j < 4; j++) sacc[i][j] = 0.f;
#pragma unroll
        for (int ks = 0; ks < 8; ks++) {
#pragma unroll
            for (int nt = 0; nt < 4; nt++) {
                unsigned b0 = __float_as_uint(sK[(nt * 8 + gid) * 68 + ks * 8 + tig]);
                unsigned b1 = __float_as_uint(sK[(nt * 8 + gid) * 68 + ks * 8 + tig + 4]);
                mma_tf32(sacc[nt][0], sacc[nt][1], sacc[nt][2], sacc[nt][3],
                         qa[ks][0], qa[ks][1], qa[ks][2], qa[ks][3], b0, b1);
            }
        }

        // ---- online softmax (rows r = w*16+gid and r+8) ----
        float cm0 = -1e30f, cm1 = -1e30f;
#pragma unroll
        for (int nt = 0; nt < 4; nt++) {
            cm0 = fmaxf(cm0, fmaxf(sacc[nt][0], sacc[nt][1]));
            cm1 = fmaxf(cm1, fmaxf(sacc[nt][2], sacc[nt][3]));
        }
        cm0 = fmaxf(cm0, __shfl_xor_sync(0xffffffffu, cm0, 1));
        cm0 = fmaxf(cm0, __shfl_xor_sync(0xffffffffu, cm0, 2));
        cm1 = fmaxf(cm1, __shfl_xor_sync(0xffffffffu, cm1, 1));
        cm1 = fmaxf(cm1, __shfl_xor_sync(0xffffffffu, cm1, 2));
        float mn0 = fmaxf(m0r, cm0), mn1 = fmaxf(m1r, cm1);
        float al0 = __expf(m0r - mn0), al1 = __expf(m1r - mn1);
        float ps0 = 0.f, ps1 = 0.f;
        int r0off = (w * 16 + gid) * 36;
        int r1off = (w * 16 + gid + 8) * 36;
#pragma unroll
        for (int nt = 0; nt < 4; nt++) {
            float p0 = __expf(sacc[nt][0] - mn0);
            float p1 = __expf(sacc[nt][1] - mn0);
            float p2 = __expf(sacc[nt][2] - mn1);
            float p3 = __expf(sacc[nt][3] - mn1);
            ps0 += p0 + p1;
            ps1 += p2 + p3;
            int co = nt * 8 + 2 * tig;
            float2 e0, e1;
            e0.x = __uint_as_float(f2tf(p0)); e0.y = __uint_as_float(f2tf(p1));
            e1.x = __uint_as_float(f2tf(p2)); e1.y = __uint_as_float(f2tf(p3));
            *(float2*)&sP[r0off + co] = e0;
            *(float2*)&sP[r1off + co] = e1;
        }
        ps0 += __shfl_xor_sync(0xffffffffu, ps0, 1);
        ps0 += __shfl_xor_sync(0xffffffffu, ps0, 2);
        ps1 += __shfl_xor_sync(0xffffffffu, ps1, 1);
        ps1 += __shfl_xor_sync(0xffffffffu, ps1, 2);
        l0 = l0 * al0 + ps0;  m0r = mn0;
        l1 = l1 * al1 + ps1;  m1r = mn1;
#pragma unroll
        for (int nt = 0; nt < 8; nt++) {
            oacc[nt][0] *= al0; oacc[nt][1] *= al0;
            oacc[nt][2] *= al1; oacc[nt][3] *= al1;
        }
        __syncwarp();   // P visible within warp

        // ---- phase 2: O[16x64] += P[16x32] * V[32x64] ----
#pragma unroll
        for (int ks = 0; ks < 4; ks++) {
            unsigned a0 = __float_as_uint(sP[r0off + ks * 8 + tig]);
            unsigned a1 = __float_as_uint(sP[r1off + ks * 8 + tig]);
            unsigned a2 = __float_as_uint(sP[r0off + ks * 8 + tig + 4]);
            unsigned a3 = __float_as_uint(sP[r1off + ks * 8 + tig + 4]);
#pragma unroll
            for (int nt = 0; nt < 8; nt++) {
                unsigned b0 = __float_as_uint(sV[(ks * 8 + tig)     * 72 + nt * 8 + gid]);
                unsigned b1 = __float_as_uint(sV[(ks * 8 + tig + 4) * 72 + nt * 8 + gid]);
                mma_tf32(oacc[nt][0], oacc[nt][1], oacc[nt][2], oacc[nt][3],
                         a0, a1, a2, a3, b0, b1);
            }
        }
    }

    // ---- epilogue: normalize and write (heads concatenated in C) ----
    float inv0 = 1.f / l0, inv1 = 1.f / l1;
    float* ob = O + ((size_t)(b * NQ + n0 + w * 16)) * C_DIM + h * DH;
#pragma unroll
    for (int nt = 0; nt < 8; nt++) {
        int d = nt * 8 + 2 * tig;
        float2 r0v, r1v;
        r0v.x = oacc[nt][0] * inv0; r0v.y = oacc[nt][1] * inv0;
        r1v.x = oacc[nt][2] * inv1; r1v.y = oacc[nt][3] * inv1;
        *(float2*)(ob + (size_t)gid       * C_DIM + d) = r0v;
        *(float2*)(ob + (size_t)(gid + 8) * C_DIM + d) = r1v;
    }
}

// ---------------------------------------------------------------------------
// Launch. Inputs: x, Wq, Wk, Wv, Wproj, sr_kernel, sr_bias, gamma, beta.
// ---------------------------------------------------------------------------
extern "C" void kernel_launch(void* const* d_in, const int* in_sizes, int n_in,
                              void* d_out, int out_size) {
    const float* x     = (const float*)d_in[0];
    const float* Wq    = (const float*)d_in[1];
    const float* Wk    = (const float*)d_in[2];
    const float* Wv    = (const float*)d_in[3];
    const float* Wp    = (const float*)d_in[4];
    const float* Wsr   = (const float*)d_in[5];
    const float* bias  = (const float*)d_in[6];
    const float* gamma = (const float*)d_in[7];
    const float* beta  = (const float*)d_in[8];

    float *q, *xr, *k, *v, *ao;
    cudaGetSymbolAddress((void**)&q,  g_q);
    cudaGetSymbolAddress((void**)&xr, g_xr);
    cudaGetSymbolAddress((void**)&k,  g_k);
    cudaGetSymbolAddress((void**)&v,  g_v);
    cudaGetSymbolAddress((void**)&ao, g_ao);

    gemm128_kernel<<<(BATCH * NQ) / 64, 256>>>(x, Wq, q, BATCH * NQ);            // Q proj
    conv_ln_kernel<<<(BATCH * NKV) / 32, 256>>>(x, Wsr, bias, gamma, beta, xr);  // SR + LN
    gemm128_kernel<<<(BATCH * NKV) / 64, 256>>>(xr, Wk, k, BATCH * NKV);         // K proj
    gemm128_kernel<<<(BATCH * NKV) / 64, 256>>>(xr, Wv, v, BATCH * NKV);         // V proj
    attn_mma_kernel<<<dim3(NQ / QTILE, HEADS, BATCH), 256>>>(q, k, v, ao);       // attention
    gemm128_kernel<<<(BATCH * NQ) / 64, 256>>>(ao, Wp, (float*)d_out, BATCH * NQ); // out proj
}

// round 7
// speedup vs baseline: 6.5017x; 1.3622x over previous
#include <cuda_runtime.h>
#include <math.h>

// ---------------------------------------------------------------------------
// Problem constants: B=4, N=16384 (H=W=128), C=128, HEADS=2, dh=64, SR=4
// ---------------------------------------------------------------------------
#define BATCH   4
#define NQ      16384
#define C_DIM   128
#define HEADS   2
#define DH      64
#define NKV     1024
#define QTILE   128
#define KCH     32
#define KCONV   2048

// Scratch (allocation-free rule: __device__ globals)
__device__ float g_q  [BATCH * NQ  * C_DIM];
__device__ float g_xr [BATCH * NKV * C_DIM];
__device__ float g_k  [BATCH * NKV * C_DIM];
__device__ float g_v  [BATCH * NKV * C_DIM];
__device__ float g_ao [BATCH * NQ  * C_DIM];
__device__ float g_wtq[C_DIM * C_DIM];     // transposed tf32 weights [n][k]
__device__ float g_wtk[C_DIM * C_DIM];
__device__ float g_wtv[C_DIM * C_DIM];
__device__ float g_wtp[C_DIM * C_DIM];
__device__ float g_wct[C_DIM * KCONV];     // conv weight transposed [n][k]

// ---------------------------------------------------------------------------
// tf32 helpers (fragment mappings validated in R5 attention kernel)
// ---------------------------------------------------------------------------
__device__ __forceinline__ unsigned f2tf(float x) {
    unsigned r;
    asm("cvt.rna.tf32.f32 %0, %1;" : "=r"(r) : "f"(x));
    return r;
}
__device__ __forceinline__ float f2tff(float x) {
    return __uint_as_float(f2tf(x));
}
__device__ __forceinline__ void mma_tf32(float& d0, float& d1, float& d2, float& d3,
                                         unsigned a0, unsigned a1, unsigned a2, unsigned a3,
                                         unsigned b0, unsigned b1) {
    asm volatile(
        "mma.sync.aligned.m16n8k8.row.col.f32.tf32.tf32.f32 "
        "{%0,%1,%2,%3},{%4,%5,%6,%7},{%8,%9},{%0,%1,%2,%3};"
        : "+f"(d0), "+f"(d1), "+f"(d2), "+f"(d3)
        : "r"(a0), "r"(a1), "r"(a2), "r"(a3), "r"(b0), "r"(b1));
}

// ---------------------------------------------------------------------------
// Weight prep: src [K][128] row-major -> dst [128][K], tf32-rounded.
// grid (K/32, 4), block (32, 8).
// ---------------------------------------------------------------------------
__global__ void transpose_tf32_kernel(const float* __restrict__ src,
                                      float* __restrict__ dst, int K) {
    __shared__ float tile[32][33];
    int kb = blockIdx.x << 5, nb = blockIdx.y << 5;
    int tx = threadIdx.x, ty = threadIdx.y;
#pragma unroll
    for (int r = 0; r < 32; r += 8)
        tile[ty + r][tx] = src[(size_t)(kb + ty + r) * 128 + nb + tx];
    __syncthreads();
#pragma unroll
    for (int r = 0; r < 32; r += 8)
        dst[(size_t)(nb + ty + r) * K + kb + tx] = f2tff(tile[tx][ty + r]);
}

// ---------------------------------------------------------------------------
// tf32 tensor-core GEMM: out[M,128] = A[M,128] @ W  (Wt pre-transposed [n][k])
// BM=128, 256 threads / 8 warps, warp w owns rows w*16..+16, all 128 cols.
// smem stride 36 -> fragment-read bank = (4*row + k) % 32, unique per lane.
// ---------------------------------------------------------------------------
__global__ __launch_bounds__(256)
void gemm_tf32_kernel(const float* __restrict__ A, const float* __restrict__ Wt,
                      float* __restrict__ out) {
    __shared__ float sA[128 * 36];
    __shared__ float sW[128 * 36];
    int m0 = blockIdx.x << 7;
    int tid = threadIdx.x;
    int w = tid >> 5, lane = tid & 31;
    int gid = lane >> 2, tig = lane & 3;

    float oacc[16][4];
#pragma unroll
    for (int i = 0; i < 16; i++)
#pragma unroll
        for (int j = 0; j < 4; j++) oacc[i][j] = 0.f;

#pragma unroll 1
    for (int kc = 0; kc < 4; kc++) {
        int k0 = kc << 5;
        __syncthreads();
#pragma unroll
        for (int i = 0; i < 4; i++) {
            int f = tid + (i << 8);
            int row = f >> 3, c4 = f & 7;
            float4 av = *(const float4*)&A[(size_t)(m0 + row) * 128 + k0 + (c4 << 2)];
            av.x = f2tff(av.x); av.y = f2tff(av.y); av.z = f2tff(av.z); av.w = f2tff(av.w);
            *(float4*)&sA[row * 36 + (c4 << 2)] = av;
            float4 wv = *(const float4*)&Wt[(size_t)row * 128 + k0 + (c4 << 2)];
            *(float4*)&sW[row * 36 + (c4 << 2)] = wv;   // already tf32
        }
        __syncthreads();
#pragma unroll
        for (int ks = 0; ks < 4; ks++) {
            int ko = (ks << 3) + tig;
            unsigned a0 = __float_as_uint(sA[(w * 16 + gid)     * 36 + ko]);
            unsigned a1 = __float_as_uint(sA[(w * 16 + gid + 8) * 36 + ko]);
            unsigned a2 = __float_as_uint(sA[(w * 16 + gid)     * 36 + ko + 4]);
            unsigned a3 = __float_as_uint(sA[(w * 16 + gid + 8) * 36 + ko + 4]);
#pragma unroll
            for (int nt = 0; nt < 16; nt++) {
                unsigned b0 = __float_as_uint(sW[(nt * 8 + gid) * 36 + ko]);
                unsigned b1 = __float_as_uint(sW[(nt * 8 + gid) * 36 + ko + 4]);
                mma_tf32(oacc[nt][0], oacc[nt][1], oacc[nt][2], oacc[nt][3],
                         a0, a1, a2, a3, b0, b1);
            }
        }
    }
    size_t r0 = (size_t)(m0 + w * 16 + gid) * 128;
    size_t r1 = r0 + 8 * 128;
#pragma unroll
    for (int nt = 0; nt < 16; nt++) {
        int c = nt * 8 + 2 * tig;
        *(float2*)&out[r0 + c] = make_float2(oacc[nt][0], oacc[nt][1]);
        *(float2*)&out[r1 + c] = make_float2(oacc[nt][2], oacc[nt][3]);
    }
}

// ---------------------------------------------------------------------------
// tf32 conv (4x4 stride-4 patch GEMM, K=2048) + bias + LayerNorm.
// BM=32 -> 128 blocks. 8 warps: rg=w&1 (16-row group), cg=w>>1 (32-col group).
// Each k-chunk (32) = one kernel pixel (kh,kw) x 32 input channels.
// ---------------------------------------------------------------------------
__global__ __launch_bounds__(256)
void conv_ln_tf32_kernel(const float* __restrict__ x, const float* __restrict__ Wct,
                         const float* __restrict__ bias, const float* __restrict__ gamma,
                         const float* __restrict__ beta, float* __restrict__ out) {
    __shared__ float sA[32 * 36];
    __shared__ float sW[128 * 36];
    __shared__ float sred[32 * 4], sredq[32 * 4];
    __shared__ float sMu[32], sRs[32];

    int m0 = blockIdx.x << 5;
    int tid = threadIdx.x;
    int w = tid >> 5, lane = tid & 31;
    int gid = lane >> 2, tig = lane & 3;
    int rg = w & 1, cg = w >> 1;

    float oacc[4][4];
#pragma unroll
    for (int i = 0; i < 4; i++)
#pragma unroll
        for (int j = 0; j < 4; j++) oacc[i][j] = 0.f;

#pragma unroll 1
    for (int kc = 0; kc < 64; kc++) {
        int k0  = kc << 5;
        int kh  = k0 >> 9;
        int kw  = (k0 >> 7) & 3;
        int ci0 = k0 & 127;
        __syncthreads();
        {   // gather A chunk: 32 rows x 32 channels (1 float4 / thread)
            int row = tid >> 3, c4 = tid & 7;
            int m  = m0 + row;
            int b  = m >> 10, pos = m & 1023, oh = pos >> 5, ow = pos & 31;
            const float* px = x + ((size_t)((b * 128 + (oh << 2) + kh) * 128 + (ow << 2) + kw)) * 128 + ci0;
            float4 av = *(const float4*)(px + (c4 << 2));
            av.x = f2tff(av.x); av.y = f2tff(av.y); av.z = f2tff(av.z); av.w = f2tff(av.w);
            *(float4*)&sA[row * 36 + (c4 << 2)] = av;
        }
#pragma unroll
        for (int i = 0; i < 4; i++) {   // W chunk [n=128][k=32]
            int f = tid + (i << 8);
            int n = f >> 3, c4 = f & 7;
            float4 wv = *(const float4*)&Wct[(size_t)n * KCONV + k0 + (c4 << 2)];
            *(float4*)&sW[n * 36 + (c4 << 2)] = wv;
        }
        __syncthreads();
#pragma unroll
        for (int ks = 0; ks < 4; ks++) {
            int ko = (ks << 3) + tig;
            unsigned a0 = __float_as_uint(sA[(rg * 16 + gid)     * 36 + ko]);
            unsigned a1 = __float_as_uint(sA[(rg * 16 + gid + 8) * 36 + ko]);
            unsigned a2 = __float_as_uint(sA[(rg * 16 + gid)     * 36 + ko + 4]);
            unsigned a3 = __float_as_uint(sA[(rg * 16 + gid + 8) * 36 + ko + 4]);
#pragma unroll
            for (int nt = 0; nt < 4; nt++) {
                unsigned b0 = __float_as_uint(sW[(cg * 32 + nt * 8 + gid) * 36 + ko]);
                unsigned b1 = __float_as_uint(sW[(cg * 32 + nt * 8 + gid) * 36 + ko + 4]);
                mma_tf32(oacc[nt][0], oacc[nt][1], oacc[nt][2], oacc[nt][3],
                         a0, a1, a2, a3, b0, b1);
            }
        }
    }

    // ---- epilogue: +bias, LayerNorm over C=128 ----
    float s0 = 0.f, s0q = 0.f, s1 = 0.f, s1q = 0.f;
#pragma unroll
    for (int nt = 0; nt < 4; nt++) {
        int c = cg * 32 + nt * 8 + 2 * tig;
        float b0v = bias[c], b1v = bias[c + 1];
        oacc[nt][0] += b0v; oacc[nt][1] += b1v;
        oacc[nt][2] += b0v; oacc[nt][3] += b1v;
        s0  += oacc[nt][0] + oacc[nt][1];
        s0q += oacc[nt][0] * oacc[nt][0] + oacc[nt][1] * oacc[nt][1];
        s1  += oacc[nt][2] + oacc[nt][3];
        s1q += oacc[nt][2] * oacc[nt][2] + oacc[nt][3] * oacc[nt][3];
    }
    s0  += __shfl_xor_sync(0xffffffffu, s0, 1);  s0  += __shfl_xor_sync(0xffffffffu, s0, 2);
    s0q += __shfl_xor_sync(0xffffffffu, s0q, 1); s0q += __shfl_xor_sync(0xffffffffu, s0q, 2);
    s1  += __shfl_xor_sync(0xffffffffu, s1, 1);  s1  += __shfl_xor_sync(0xffffffffu, s1, 2);
    s1q += __shfl_xor_sync(0xffffffffu, s1q, 1); s1q += __shfl_xor_sync(0xffffffffu, s1q, 2);
    if (tig == 0) {
        int r0 = rg * 16 + gid;
        sred [r0 * 4 + cg] = s0;  sredq[r0 * 4 + cg] = s0q;
        sred [(r0 + 8) * 4 + cg] = s1;  sredq[(r0 + 8) * 4 + cg] = s1q;
    }
    __syncthreads();
    if (tid < 32) {
        float s = 0.f, sq = 0.f;
#pragma unroll
        for (int t = 0; t < 4; t++) { s += sred[tid * 4 + t]; sq += sredq[tid * 4 + t]; }
        float mu  = s * 0.0078125f;
        float var = sq * 0.0078125f - mu * mu;
        sMu[tid] = mu;
        sRs[tid] = rsqrtf(var + 1e-6f);
    }
    __syncthreads();
    int r0 = rg * 16 + gid, r1 = r0 + 8;
    float mu0 = sMu[r0], rs0 = sRs[r0], mu1 = sMu[r1], rs1 = sRs[r1];
#pragma unroll
    for (int nt = 0; nt < 4; nt++) {
        int c = cg * 32 + nt * 8 + 2 * tig;
        float g0 = gamma[c], g1 = gamma[c + 1], be0 = beta[c], be1 = beta[c + 1];
        *(float2*)&out[(size_t)(m0 + r0) * 128 + c] =
            make_float2((oacc[nt][0] - mu0) * rs0 * g0 + be0,
                        (oacc[nt][1] - mu0) * rs0 * g1 + be1);
        *(float2*)&out[(size_t)(m0 + r1) * 128 + c] =
            make_float2((oacc[nt][2] - mu1) * rs1 * g0 + be0,
                        (oacc[nt][3] - mu1) * rs1 * g1 + be1);
    }
}

// ---------------------------------------------------------------------------
// tf32 tensor-core flash attention (unchanged from R5 — passed @ rel 2.5e-4)
// ---------------------------------------------------------------------------
__global__ __launch_bounds__(256)
void attn_mma_kernel(const float* __restrict__ Q, const float* __restrict__ K,
                     const float* __restrict__ V, float* __restrict__ O) {
    __shared__ float sK[KCH * 68];
    __shared__ float sV[KCH * 72];
    __shared__ float sP[QTILE * 36];

    int b  = blockIdx.z, h = blockIdx.y;
    int n0 = blockIdx.x * QTILE;
    int tid  = threadIdx.x;
    int w    = tid >> 5;
    int lane = tid & 31;
    int gid  = lane >> 2;
    int tig  = lane & 3;

    unsigned qa[8][4];
    {
        const float* qb = Q + ((size_t)(b * NQ + n0 + w * 16)) * C_DIM + h * DH;
#pragma unroll
        for (int ks = 0; ks < 8; ks++) {
            int c = ks * 8 + tig;
            qa[ks][0] = f2tf(qb[(size_t)gid       * C_DIM + c    ] * 0.125f);
            qa[ks][1] = f2tf(qb[(size_t)(gid + 8) * C_DIM + c    ] * 0.125f);
            qa[ks][2] = f2tf(qb[(size_t)gid       * C_DIM + c + 4] * 0.125f);
            qa[ks][3] = f2tf(qb[(size_t)(gid + 8) * C_DIM + c + 4] * 0.125f);
        }
    }

    const float* kb_ = K + (size_t)(b * NKV) * C_DIM + h * DH;
    const float* vb_ = V + (size_t)(b * NKV) * C_DIM + h * DH;

    float oacc[8][4];
#pragma unroll
    for (int i = 0; i < 8; i++)
#pragma unroll
        for (int j = 0; j < 4; j++) oacc[i][j] = 0.f;
    float m0r = -1e30f, m1r = -1e30f, l0 = 0.f, l1 = 0.f;

#pragma unroll 1
    for (int kc = 0; kc < NKV / KCH; kc++) {
        __syncthreads();
#pragma unroll
        for (int i = 0; i < 2; i++) {
            int f = tid + (i << 8);
            int row = f >> 4, c4 = f & 15;
            size_t go = (size_t)(kc * KCH + row) * C_DIM + (c4 << 2);
            float4 kv = *(const float4*)(kb_ + go);
            float4 vv = *(const float4*)(vb_ + go);
            float4 kt, vt;
            kt.x = f2tff(kv.x); kt.y = f2tff(kv.y); kt.z = f2tff(kv.z); kt.w = f2tff(kv.w);
            vt.x = f2tff(vv.x); vt.y = f2tff(vv.y); vt.z = f2tff(vv.z); vt.w = f2tff(vv.w);
            *(float4*)&sK[row * 68 + (c4 << 2)] = kt;
            *(float4*)&sV[row * 72 + (c4 << 2)] = vt;
        }
        __syncthreads();

        float sacc[4][4];
#pragma unroll
        for (int i = 0; i < 4; i++)
#pragma unroll
            for (int j = 0; j < 4; j++) sacc[i][j] = 0.f;
#pragma unroll
        for (int ks = 0; ks < 8; ks++) {
#pragma unroll
            for (int nt = 0; nt < 4; nt++) {
                unsigned b0 = __float_as_uint(sK[(nt * 8 + gid) * 68 + ks * 8 + tig]);
                unsigned b1 = __float_as_uint(sK[(nt * 8 + gid) * 68 + ks * 8 + tig + 4]);
                mma_tf32(sacc[nt][0], sacc[nt][1], sacc[nt][2], sacc[nt][3],
                         qa[ks][0], qa[ks][1], qa[ks][2], qa[ks][3], b0, b1);
            }
        }

        float cm0 = -1e30f, cm1 = -1e30f;
#pragma unroll
        for (int nt = 0; nt < 4; nt++) {
            cm0 = fmaxf(cm0, fmaxf(sacc[nt][0], sacc[nt][1]));
            cm1 = fmaxf(cm1, fmaxf(sacc[nt][2], sacc[nt][3]));
        }
        cm0 = fmaxf(cm0, __shfl_xor_sync(0xffffffffu, cm0, 1));
        cm0 = fmaxf(cm0, __shfl_xor_sync(0xffffffffu, cm0, 2));
        cm1 = fmaxf(cm1, __shfl_xor_sync(0xffffffffu, cm1, 1));
        cm1 = fmaxf(cm1, __shfl_xor_sync(0xffffffffu, cm1, 2));
        float mn0 = fmaxf(m0r, cm0), mn1 = fmaxf(m1r, cm1);
        float al0 = __expf(m0r - mn0), al1 = __expf(m1r - mn1);
        float ps0 = 0.f, ps1 = 0.f;
        int r0off = (w * 16 + gid) * 36;
        int r1off = (w * 16 + gid + 8) * 36;
#pragma unroll
        for (int nt = 0; nt < 4; nt++) {
            float p0 = __expf(sacc[nt][0] - mn0);
            float p1 = __expf(sacc[nt][1] - mn0);
            float p2 = __expf(sacc[nt][2] - mn1);
            float p3 = __expf(sacc[nt][3] - mn1);
            ps0 += p0 + p1;
            ps1 += p2 + p3;
            int co = nt * 8 + 2 * tig;
            float2 e0, e1;
            e0.x = f2tff(p0); e0.y = f2tff(p1);
            e1.x = f2tff(p2); e1.y = f2tff(p3);
            *(float2*)&sP[r0off + co] = e0;
            *(float2*)&sP[r1off + co] = e1;
        }
        ps0 += __shfl_xor_sync(0xffffffffu, ps0, 1);
        ps0 += __shfl_xor_sync(0xffffffffu, ps0, 2);
        ps1 += __shfl_xor_sync(0xffffffffu, ps1, 1);
        ps1 += __shfl_xor_sync(0xffffffffu, ps1, 2);
        l0 = l0 * al0 + ps0;  m0r = mn0;
        l1 = l1 * al1 + ps1;  m1r = mn1;
#pragma unroll
        for (int nt = 0; nt < 8; nt++) {
            oacc[nt][0] *= al0; oacc[nt][1] *= al0;
            oacc[nt][2] *= al1; oacc[nt][3] *= al1;
        }
        __syncwarp();

#pragma unroll
        for (int ks = 0; ks < 4; ks++) {
            unsigned a0 = __float_as_uint(sP[r0off + ks * 8 + tig]);
            unsigned a1 = __float_as_uint(sP[r1off + ks * 8 + tig]);
            unsigned a2 = __float_as_uint(sP[r0off + ks * 8 + tig + 4]);
            unsigned a3 = __float_as_uint(sP[r1off + ks * 8 + tig + 4]);
#pragma unroll
            for (int nt = 0; nt < 8; nt++) {
                unsigned b0 = __float_as_uint(sV[(ks * 8 + tig)     * 72 + nt * 8 + gid]);
                unsigned b1 = __float_as_uint(sV[(ks * 8 + tig + 4) * 72 + nt * 8 + gid]);
                mma_tf32(oacc[nt][0], oacc[nt][1], oacc[nt][2], oacc[nt][3],
                         a0, a1, a2, a3, b0, b1);
            }
        }
    }

    float inv0 = 1.f / l0, inv1 = 1.f / l1;
    float* ob = O + ((size_t)(b * NQ + n0 + w * 16)) * C_DIM + h * DH;
#pragma unroll
    for (int nt = 0; nt < 8; nt++) {
        int d = nt * 8 + 2 * tig;
        float2 r0v, r1v;
        r0v.x = oacc[nt][0] * inv0; r0v.y = oacc[nt][1] * inv0;
        r1v.x = oacc[nt][2] * inv1; r1v.y = oacc[nt][3] * inv1;
        *(float2*)(ob + (size_t)gid       * C_DIM + d) = r0v;
        *(float2*)(ob + (size_t)(gid + 8) * C_DIM + d) = r1v;
    }
}

// ---------------------------------------------------------------------------
// Launch. Inputs: x, Wq, Wk, Wv, Wproj, sr_kernel, sr_bias, gamma, beta.
// ---------------------------------------------------------------------------
extern "C" void kernel_launch(void* const* d_in, const int* in_sizes, int n_in,
                              void* d_out, int out_size) {
    const float* x     = (const float*)d_in[0];
    const float* Wq    = (const float*)d_in[1];
    const float* Wk    = (const float*)d_in[2];
    const float* Wv    = (const float*)d_in[3];
    const float* Wp    = (const float*)d_in[4];
    const float* Wsr   = (const float*)d_in[5];
    const float* bias  = (const float*)d_in[6];
    const float* gamma = (const float*)d_in[7];
    const float* beta  = (const float*)d_in[8];

    float *q, *xr, *k, *v, *ao, *wtq, *wtk, *wtv, *wtp, *wct;
    cudaGetSymbolAddress((void**)&q,   g_q);
    cudaGetSymbolAddress((void**)&xr,  g_xr);
    cudaGetSymbolAddress((void**)&k,   g_k);
    cudaGetSymbolAddress((void**)&v,   g_v);
    cudaGetSymbolAddress((void**)&ao,  g_ao);
    cudaGetSymbolAddress((void**)&wtq, g_wtq);
    cudaGetSymbolAddress((void**)&wtk, g_wtk);
    cudaGetSymbolAddress((void**)&wtv, g_wtv);
    cudaGetSymbolAddress((void**)&wtp, g_wtp);
    cudaGetSymbolAddress((void**)&wct, g_wct);

    dim3 tb(32, 8);
    transpose_tf32_kernel<<<dim3(4, 4),  tb>>>(Wq,  wtq, 128);
    transpose_tf32_kernel<<<dim3(4, 4),  tb>>>(Wk,  wtk, 128);
    transpose_tf32_kernel<<<dim3(4, 4),  tb>>>(Wv,  wtv, 128);
    transpose_tf32_kernel<<<dim3(4, 4),  tb>>>(Wp,  wtp, 128);
    transpose_tf32_kernel<<<dim3(64, 4), tb>>>(Wsr, wct, KCONV);

    gemm_tf32_kernel<<<(BATCH * NQ) / 128, 256>>>(x, wtq, q);                   // Q proj
    conv_ln_tf32_kernel<<<(BATCH * NKV) / 32, 256>>>(x, wct, bias, gamma, beta, xr);
    gemm_tf32_kernel<<<(BATCH * NKV) / 128, 256>>>(xr, wtk, k);                 // K proj
    gemm_tf32_kernel<<<(BATCH * NKV) / 128, 256>>>(xr, wtv, v);                 // V proj
    attn_mma_kernel<<<dim3(NQ / QTILE, HEADS, BATCH), 256>>>(q, k, v, ao);      // attention
    gemm_tf32_kernel<<<(BATCH * NQ) / 128, 256>>>(ao, wtp, (float*)d_out);      // out proj
}